// round 11
// baseline (speedup 1.0000x reference)
#include <cuda_runtime.h>
#include <cuda_bf16.h>
#include <math.h>
#include <stdint.h>

#define NN 50000
#define NROWPAD 50048
#define EE 800000
#define FULLM 0xffffffffu

// ---------------- static scratch (no allocation allowed) ----------------
__device__ __align__(128) float g_bufA[NROWPAD * 256];      // fp32 GEMM outputs
__device__ __align__(128) __nv_bfloat16 g_xhi[NROWPAD * 128];
__device__ __align__(128) __nv_bfloat16 g_xlo[NROWPAD * 128];
__device__ __align__(128) __nv_bfloat16 g_hhi[NROWPAD * 256];
__device__ __align__(128) __nv_bfloat16 g_hlo[NROWPAD * 256];
__device__ __align__(128) __nv_bfloat16 g_B1hi[256 * 128];
__device__ __align__(128) __nv_bfloat16 g_B1lo[256 * 128];
__device__ __align__(128) __nv_bfloat16 g_B2hi[256 * 256];
__device__ __align__(128) __nv_bfloat16 g_B2lo[256 * 256];
__device__ __align__(128) __nv_bfloat16 g_Bthi[256 * 256];
__device__ __align__(128) __nv_bfloat16 g_Btlo[256 * 256];
__device__ float g_as[NN * 8];
__device__ float g_ad[NN * 8];
__device__ float g_as4[NN * 4];
__device__ float g_ad4[NN * 4];
__device__ float g_acs[224];
__device__ float g_acd[224];
__device__ float g_bc[224];
__device__ int g_deg[NN];
__device__ int g_rowp[NN + 1];
__device__ int g_cursor[NN];
__device__ int g_col[EE];

// ---------------- helpers ----------------
__device__ __forceinline__ float wredsum(float v) {
#pragma unroll
    for (int o = 16; o > 0; o >>= 1) v += __shfl_xor_sync(FULLM, v, o);
    return v;
}
__device__ __forceinline__ float wredmax(float v) {
#pragma unroll
    for (int o = 16; o > 0; o >>= 1) v = fmaxf(v, __shfl_xor_sync(FULLM, v, o));
    return v;
}
__device__ __forceinline__ float lrelu(float e) { return e > 0.f ? e : 0.2f * e; }
__device__ __forceinline__ unsigned su32(const void* p) {
    unsigned r;
    asm("{ .reg .u64 t; cvta.to.shared.u64 t, %1; cvt.u32.u64 %0, t; }" : "=r"(r) : "l"(p));
    return r;
}
__device__ __forceinline__ void splitbf(float v, __nv_bfloat16& h, __nv_bfloat16& l) {
    h = __float2bfloat16(v);
    l = __float2bfloat16(v - __bfloat162float(h));
}
__device__ __forceinline__ uint32_t pkbf(__nv_bfloat16 a, __nv_bfloat16 b) {
    __nv_bfloat162 t(a, b);
    return *(uint32_t*)&t;
}
__device__ __forceinline__ void cpa16b(uint32_t dst, const void* src) {
    asm volatile("cp.async.ca.shared.global [%0], [%1], 16;" :: "r"(dst), "l"(src));
}
#define CPA_COMMIT() asm volatile("cp.async.commit_group;" ::: "memory")
#define CPA_WAIT1()  asm volatile("cp.async.wait_group 1;" ::: "memory")

__device__ __forceinline__ void ldmx4(uint32_t* r, uint32_t addr) {
    asm volatile("ldmatrix.sync.aligned.m8n8.x4.shared.b16 {%0,%1,%2,%3}, [%4];"
                 : "=r"(r[0]), "=r"(r[1]), "=r"(r[2]), "=r"(r[3]) : "r"(addr));
}
__device__ __forceinline__ void mma16816(float* c, const uint32_t* a,
                                         uint32_t b0, uint32_t b1) {
    asm volatile(
        "mma.sync.aligned.m16n8k16.row.col.f32.bf16.bf16.f32 "
        "{%0,%1,%2,%3}, {%4,%5,%6,%7}, {%8,%9}, {%0,%1,%2,%3};"
        : "+f"(c[0]), "+f"(c[1]), "+f"(c[2]), "+f"(c[3])
        : "r"(a[0]), "r"(a[1]), "r"(a[2]), "r"(a[3]), "r"(b0), "r"(b1));
}

// ---------------- CSR build ----------------
__global__ void zero_int(int* p, int n) {
    int i = blockIdx.x * blockDim.x + threadIdx.x;
    if (i < n) p[i] = 0;
}
__global__ void count_deg(const int* __restrict__ ei, int E, int* deg) {
    int e = blockIdx.x * blockDim.x + threadIdx.x;
    if (e < E) atomicAdd(&deg[ei[E + e]], 1);
}
__global__ void scan_block(const int* __restrict__ deg, int* __restrict__ rowp,
                           int* __restrict__ cursor, int n) {
    __shared__ int sm[1024];
    int tid = threadIdx.x;
    int chunk = (n + 1023) >> 10;
    int start = tid * chunk;
    int s = 0;
    for (int i = 0; i < chunk; i++) { int id = start + i; if (id < n) s += deg[id]; }
    sm[tid] = s; __syncthreads();
    for (int o = 1; o < 1024; o <<= 1) {
        int t = (tid >= o) ? sm[tid - o] : 0;
        __syncthreads();
        sm[tid] += t;
        __syncthreads();
    }
    int run = sm[tid] - s;
    for (int i = 0; i < chunk; i++) {
        int id = start + i;
        if (id < n) { rowp[id] = run; cursor[id] = run; run += deg[id]; }
    }
    if (tid == 1023) rowp[n] = sm[1023];
}
__global__ void fill_col(const int* __restrict__ ei, int E, int* cursor, int* __restrict__ col) {
    int e = blockIdx.x * blockDim.x + threadIdx.x;
    if (e < E) {
        int s = ei[e];
        int d = ei[E + e];
        int p = atomicAdd(&cursor[d], 1);
        col[p] = s;
    }
}

// ---------------- input conversion fp32 -> bf16 hi/lo ----------------
__global__ void convert_x(const float* __restrict__ x, __nv_bfloat16* __restrict__ xhi,
                          __nv_bfloat16* __restrict__ xlo, int n) {
    int idx = blockIdx.x * blockDim.x + threadIdx.x;   // 4 floats each
    if (idx >= n * 32) return;
    int row = idx >> 5, c4 = (idx & 31) << 2;
    float4 v = *(const float4*)(x + (size_t)row * 128 + c4);
    __nv_bfloat16 h0, l0, h1, l1, h2, l2, h3, l3;
    splitbf(v.x, h0, l0); splitbf(v.y, h1, l1);
    splitbf(v.z, h2, l2); splitbf(v.w, h3, l3);
    uint2 hw = make_uint2(pkbf(h0, h1), pkbf(h2, h3));
    uint2 lw = make_uint2(pkbf(l0, l1), pkbf(l2, l3));
    *(uint2*)(xhi + (size_t)row * 128 + c4) = hw;
    *(uint2*)(xlo + (size_t)row * 128 + c4) = lw;
}

// ---------------- weight packs: W[K][256] -> B[n][K] bf16 hi/lo (transposed) ----------
__global__ void pack_w(const float* __restrict__ W, __nv_bfloat16* __restrict__ bh,
                       __nv_bfloat16* __restrict__ bl, int K) {
    int idx = blockIdx.x * blockDim.x + threadIdx.x;
    if (idx >= 256 * K) return;
    int n = idx / K, k = idx % K;
    float v = W[(size_t)k * 256 + n];
    __nv_bfloat16 h, l;
    splitbf(v, h, l);
    bh[idx] = h; bl[idx] = l;
}
__global__ void pack_wt(const float* __restrict__ W0, const float* __restrict__ W1,
                        const float* __restrict__ W2, const float* __restrict__ W3,
                        const float* __restrict__ s0, const float* __restrict__ s1,
                        const float* __restrict__ s2, const float* __restrict__ s3,
                        const float* __restrict__ d0, const float* __restrict__ d1,
                        const float* __restrict__ d2, const float* __restrict__ d3,
                        const float* __restrict__ b0, const float* __restrict__ b1,
                        const float* __restrict__ b2, const float* __restrict__ b3,
                        __nv_bfloat16* __restrict__ bh, __nv_bfloat16* __restrict__ bl,
                        float* __restrict__ acs, float* __restrict__ acd,
                        float* __restrict__ bc) {
    int idx = blockIdx.x * blockDim.x + threadIdx.x;
    if (idx >= 256 * 256) return;
    int n = idx >> 8, k = idx & 255;
    float v = 0.f;
    if (n < 12) v = W0[k * 12 + n];
    else if (n < 42) v = W1[k * 30 + (n - 12)];
    else if (n < 102) v = W2[k * 60 + (n - 42)];
    else if (n < 222) v = W3[k * 120 + (n - 102)];
    __nv_bfloat16 h, l;
    splitbf(v, h, l);
    bh[idx] = h; bl[idx] = l;
    if (k == 0 && n < 224) {
        float s = 0.f, d = 0.f, b = 0.f;
        if (n < 12)       { s = s0[n];        d = d0[n];        b = b0[n]; }
        else if (n < 42)  { s = s1[n - 12];   d = d1[n - 12];   b = b1[n - 12]; }
        else if (n < 102) { s = s2[n - 42];   d = d2[n - 42];   b = b2[n - 42]; }
        else if (n < 222) { s = s3[n - 102];  d = d3[n - 102];  b = b3[n - 102]; }
        acs[n] = s; acd[n] = d; bc[n] = b;
    }
}

// ---------------- bf16x3 GEMM via mma.sync (persistent): C[M,Nout] = A[M,K] * W ------
// CTA tile 128x128, warp tile 32x64, K chunk 32, cp.async dbl buffer, tile loop.
// do_alpha: 0 = plain, 1 = conv per-head alpha (as/ad [M,8]),
//           2 = task alpha fused (as/ad [M,4], smem cross-warp reduction).
#define STG_ELEMS 20480
#define SMEM_BYTES (2 * STG_ELEMS * 2)

__global__ __launch_bounds__(256, 2) void gemm_mma(
    const __nv_bfloat16* __restrict__ Ah, const __nv_bfloat16* __restrict__ Al,
    const __nv_bfloat16* __restrict__ Bh, const __nv_bfloat16* __restrict__ Bl,
    float* __restrict__ C, int M, int K, int Nout, int numTiles,
    const float* __restrict__ a_s, const float* __restrict__ a_d,
    float* __restrict__ as_out, float* __restrict__ ad_out, int do_alpha) {
    extern __shared__ __nv_bfloat16 smem[];
    int tid = threadIdx.x, wid = tid >> 5, lane = tid & 31;
    int warpM = (wid & 3) * 32, warpN = (wid >> 2) * 64;
    int warpNi = wid >> 2;
    int g = lane >> 2, tg = lane & 3;

    for (int tile = blockIdx.x; tile < numTiles; tile += gridDim.x) {
        int rowBase = (tile >> 1) * 128, colBase = (tile & 1) * 128;

        float c[2][8][4];
#pragma unroll
        for (int mt = 0; mt < 2; mt++)
#pragma unroll
            for (int nt = 0; nt < 8; nt++)
#pragma unroll
                for (int j = 0; j < 4; j++) c[mt][nt][j] = 0.f;

        auto issue = [&](int t, int buf) {
            int kc = t << 5;
            uint32_t base = buf * STG_ELEMS;
#pragma unroll
            for (int i = 0; i < 2; i++) {
                int q = tid + i * 256;
                int r = q >> 2, seg = (q & 3) << 3;
                size_t aoff = (size_t)(rowBase + r) * K + kc + seg;
                size_t boff = (size_t)(colBase + r) * K + kc + seg;
                uint32_t doff = base + (uint32_t)(r * 40 + seg);
                cpa16b(su32(&smem[doff]), Ah + aoff);
                cpa16b(su32(&smem[5120 + doff]), Al + aoff);
                cpa16b(su32(&smem[10240 + doff]), Bh + boff);
                cpa16b(su32(&smem[15360 + doff]), Bl + boff);
            }
            CPA_COMMIT();
        };

        int T = K >> 5;
        issue(0, 0);
        for (int t = 0; t < T; t++) {
            if (t + 1 < T) issue(t + 1, (t + 1) & 1);
            else CPA_COMMIT();
            CPA_WAIT1();
            __syncthreads();
            uint32_t sb = su32(&smem[(t & 1) * STG_ELEMS]);
#pragma unroll
            for (int ks = 0; ks < 32; ks += 16) {
                uint32_t aHi[2][4], aLo[2][4];
#pragma unroll
                for (int mt = 0; mt < 2; mt++) {
                    uint32_t addr = sb + ((uint32_t)((warpM + mt * 16 + (lane & 15)) * 40
                                                     + ks + ((lane >> 4) & 1) * 8) << 1);
                    ldmx4(aHi[mt], addr);
                    ldmx4(aLo[mt], addr + 5120 * 2);
                }
#pragma unroll
                for (int nb = 0; nb < 4; nb++) {
                    uint32_t bHi[4], bLo[4];
                    uint32_t addr = sb + ((uint32_t)(10240
                                      + (warpN + nb * 16 + (lane & 7) + ((lane >> 4) & 1) * 8) * 40
                                      + ks + ((lane >> 3) & 1) * 8) << 1);
                    ldmx4(bHi, addr);
                    ldmx4(bLo, addr + 5120 * 2);
#pragma unroll
                    for (int mt = 0; mt < 2; mt++)
#pragma unroll
                        for (int half = 0; half < 2; half++) {
                            int nt = nb * 2 + half, s = half * 2;
                            mma16816(c[mt][nt], aHi[mt], bHi[s], bHi[s + 1]);
                            mma16816(c[mt][nt], aHi[mt], bLo[s], bLo[s + 1]);
                            mma16816(c[mt][nt], aLo[mt], bHi[s], bHi[s + 1]);
                        }
                }
            }
            __syncthreads();
        }

        // store C (fp32)
#pragma unroll
        for (int mt = 0; mt < 2; mt++) {
            int r0 = rowBase + warpM + mt * 16 + g;
#pragma unroll
            for (int nt = 0; nt < 8; nt++) {
                int col = colBase + warpN + nt * 8 + tg * 2;
                if (col < Nout) {
                    if (r0 < M)
                        *(float2*)(C + (size_t)r0 * Nout + col) = make_float2(c[mt][nt][0], c[mt][nt][1]);
                    if (r0 + 8 < M)
                        *(float2*)(C + (size_t)(r0 + 8) * Nout + col) = make_float2(c[mt][nt][2], c[mt][nt][3]);
                }
            }
        }
        if (do_alpha == 1) {
            // conv per-head alpha: warp tile 64 cols = 2 heads (32 cols each)
#pragma unroll
            for (int hh = 0; hh < 2; hh++) {
                int head = ((colBase + warpN) >> 5) + hh;
#pragma unroll
                for (int mt = 0; mt < 2; mt++) {
                    float sl = 0.f, sh = 0.f, dl = 0.f, dh = 0.f;
#pragma unroll
                    for (int q = 0; q < 4; q++) {
                        int nt = hh * 4 + q;
                        int col = colBase + warpN + nt * 8 + tg * 2;
                        float s0 = a_s[col], s1 = a_s[col + 1];
                        float d0 = a_d[col], d1 = a_d[col + 1];
                        sl += c[mt][nt][0] * s0 + c[mt][nt][1] * s1;
                        sh += c[mt][nt][2] * s0 + c[mt][nt][3] * s1;
                        dl += c[mt][nt][0] * d0 + c[mt][nt][1] * d1;
                        dh += c[mt][nt][2] * d0 + c[mt][nt][3] * d1;
                    }
                    sl += __shfl_xor_sync(FULLM, sl, 1); sl += __shfl_xor_sync(FULLM, sl, 2);
                    sh += __shfl_xor_sync(FULLM, sh, 1); sh += __shfl_xor_sync(FULLM, sh, 2);
                    dl += __shfl_xor_sync(FULLM, dl, 1); dl += __shfl_xor_sync(FULLM, dl, 2);
                    dh += __shfl_xor_sync(FULLM, dh, 1); dh += __shfl_xor_sync(FULLM, dh, 2);
                    if (tg == 0) {
                        int r0 = rowBase + warpM + mt * 16 + g;
                        if (r0 < M)     { as_out[r0 * 8 + head] = sl;       ad_out[r0 * 8 + head] = dl; }
                        if (r0 + 8 < M) { as_out[(r0 + 8) * 8 + head] = sh; ad_out[(r0 + 8) * 8 + head] = dh; }
                    }
                }
            }
        } else if (do_alpha == 2) {
            // fused task alpha: per-warp partials, cross-warpN combine via smem (deterministic)
            float ps[2][2][4], pd[2][2][4];
#pragma unroll
            for (int mt = 0; mt < 2; mt++) {
#pragma unroll
                for (int hf = 0; hf < 2; hf++)
#pragma unroll
                    for (int t = 0; t < 4; t++) { ps[mt][hf][t] = 0.f; pd[mt][hf][t] = 0.f; }
#pragma unroll
                for (int nt = 0; nt < 8; nt++) {
                    int col = colBase + warpN + nt * 8 + tg * 2;
#pragma unroll
                    for (int e = 0; e < 2; e++) {
                        int cc = col + e;
                        if (cc < 224) {
                            float sv = a_s[cc], dv = a_d[cc];
                            int ti = (cc >= 12) + (cc >= 42) + (cc >= 102);
                            ps[mt][0][ti] += c[mt][nt][e] * sv;
                            pd[mt][0][ti] += c[mt][nt][e] * dv;
                            ps[mt][1][ti] += c[mt][nt][2 + e] * sv;
                            pd[mt][1][ti] += c[mt][nt][2 + e] * dv;
                        }
                    }
                }
#pragma unroll
                for (int hf = 0; hf < 2; hf++)
#pragma unroll
                    for (int t = 0; t < 4; t++) {
                        float a = ps[mt][hf][t];
                        a += __shfl_xor_sync(FULLM, a, 1); a += __shfl_xor_sync(FULLM, a, 2);
                        ps[mt][hf][t] = a;
                        float b = pd[mt][hf][t];
                        b += __shfl_xor_sync(FULLM, b, 1); b += __shfl_xor_sync(FULLM, b, 2);
                        pd[mt][hf][t] = b;
                    }
            }
            float* red = (float*)smem;   // [128 rows][8] = 4KB, reuse pipeline smem
            if (warpNi == 0 && tg == 0) {
#pragma unroll
                for (int mt = 0; mt < 2; mt++)
#pragma unroll
                    for (int hf = 0; hf < 2; hf++) {
                        int r = warpM + mt * 16 + hf * 8 + g;
#pragma unroll
                        for (int t = 0; t < 4; t++) {
                            red[r * 8 + t] = ps[mt][hf][t];
                            red[r * 8 + 4 + t] = pd[mt][hf][t];
                        }
                    }
            }
            __syncthreads();
            if (warpNi == 1 && tg == 0) {
#pragma unroll
                for (int mt = 0; mt < 2; mt++)
#pragma unroll
                    for (int hf = 0; hf < 2; hf++) {
                        int r = warpM + mt * 16 + hf * 8 + g;
                        int gr = rowBase + r;
                        if (gr < M) {
#pragma unroll
                            for (int t = 0; t < 4; t++) {
                                as_out[gr * 4 + t] = red[r * 8 + t] + ps[mt][hf][t];
                                ad_out[gr * 4 + t] = red[r * 8 + 4 + t] + pd[mt][hf][t];
                            }
                        }
                    }
            }
        }
        __syncthreads();   // smem safe for next tile's cp.async
    }
}

// ---------------- GAT aggregation (conv): outputs bf16 hi/lo for next GEMM ----------
__global__ void gat_agg_conv(const float* __restrict__ h, const float* __restrict__ asv,
                             const float* __restrict__ adv, const int* __restrict__ rowp,
                             const int* __restrict__ col, const float* __restrict__ bias,
                             __nv_bfloat16* __restrict__ outHi,
                             __nv_bfloat16* __restrict__ outLo, int n, int do_elu) {
    __shared__ float ws[8][32][8];
    int wid = threadIdx.x >> 5, lane = threadIdx.x & 31;
    int node = blockIdx.x * 8 + wid;
    if (node >= n) return;
    int head = lane >> 2;
    float asn = 0.f, adn = 0.f;
    if (lane < 8) { asn = asv[node * 8 + lane]; adn = adv[node * 8 + lane]; }
    float m = lrelu(asn + adn);               // shift (softmax invariant); w_self = 1
    float adh[8], mh[8];
#pragma unroll
    for (int k = 0; k < 8; k++) {
        adh[k] = __shfl_sync(FULLM, adn, k);
        mh[k]  = __shfl_sync(FULLM, m, k);
    }
    const float* hs0 = h + (size_t)node * 256 + lane * 8;
    float4 acc0 = *(const float4*)hs0;
    float4 acc1 = *(const float4*)(hs0 + 4);
    float ssum = 1.f;                          // self weight per head
    int beg = rowp[node], end = rowp[node + 1];
    for (int base = beg; base < end; base += 32) {
        int i = base + lane;
        int src_l = 0;
        float4 wlo = make_float4(0.f, 0.f, 0.f, 0.f), whi = wlo;
        if (i < end) {
            src_l = col[i];
            const float4* ap = (const float4*)(asv + (size_t)src_l * 8);
            float4 a0 = ap[0], a1 = ap[1];
            wlo.x = __expf(lrelu(a0.x + adh[0]) - mh[0]);
            wlo.y = __expf(lrelu(a0.y + adh[1]) - mh[1]);
            wlo.z = __expf(lrelu(a0.z + adh[2]) - mh[2]);
            wlo.w = __expf(lrelu(a0.w + adh[3]) - mh[3]);
            whi.x = __expf(lrelu(a1.x + adh[4]) - mh[4]);
            whi.y = __expf(lrelu(a1.y + adh[5]) - mh[5]);
            whi.z = __expf(lrelu(a1.z + adh[6]) - mh[6]);
            whi.w = __expf(lrelu(a1.w + adh[7]) - mh[7]);
        }
        *(float4*)&ws[wid][lane][0] = wlo;
        *(float4*)&ws[wid][lane][4] = whi;
        __syncwarp();
        int cnt = min(32, end - base);
#pragma unroll 4
        for (int e = 0; e < cnt; e++) {
            float we = ws[wid][e][head];
            int se = __shfl_sync(FULLM, src_l, e);
            ssum += we;
            const float* hp = h + (size_t)se * 256 + lane * 8;
            float4 v0 = *(const float4*)hp, v1 = *(const float4*)(hp + 4);
            acc0.x = fmaf(we, v0.x, acc0.x); acc0.y = fmaf(we, v0.y, acc0.y);
            acc0.z = fmaf(we, v0.z, acc0.z); acc0.w = fmaf(we, v0.w, acc0.w);
            acc1.x = fmaf(we, v1.x, acc1.x); acc1.y = fmaf(we, v1.y, acc1.y);
            acc1.z = fmaf(we, v1.z, acc1.z); acc1.w = fmaf(we, v1.w, acc1.w);
        }
        __syncwarp();
    }
    float inv = 1.f / (ssum + 1e-16f);
    const float* bp = bias + lane * 8;
    float4 b0 = *(const float4*)bp, b1v = *(const float4*)(bp + 4);
    float o[8];
    o[0] = acc0.x * inv + b0.x;  o[1] = acc0.y * inv + b0.y;
    o[2] = acc0.z * inv + b0.z;  o[3] = acc0.w * inv + b0.w;
    o[4] = acc1.x * inv + b1v.x; o[5] = acc1.y * inv + b1v.y;
    o[6] = acc1.z * inv + b1v.z; o[7] = acc1.w * inv + b1v.w;
    if (do_elu) {
#pragma unroll
        for (int j = 0; j < 8; j++) o[j] = o[j] > 0.f ? o[j] : expm1f(o[j]);
    }
    uint32_t hw[4], lw[4];
#pragma unroll
    for (int j = 0; j < 4; j++) {
        __nv_bfloat16 ha, la, hb, lb;
        splitbf(o[2 * j], ha, la);
        splitbf(o[2 * j + 1], hb, lb);
        hw[j] = pkbf(ha, hb);
        lw[j] = pkbf(la, lb);
    }
    size_t off = (size_t)node * 256 + lane * 8;
    *(uint4*)(outHi + off) = make_uint4(hw[0], hw[1], hw[2], hw[3]);
    *(uint4*)(outLo + off) = make_uint4(lw[0], lw[1], lw[2], lw[3]);
}

// ---------------- fused task aggregation + log_softmax -> d_out ----------------
__global__ void gat_task(const float* __restrict__ Ht, const float* __restrict__ asv,
                         const float* __restrict__ adv, const int* __restrict__ rowp,
                         const int* __restrict__ col, const float* __restrict__ bias,
                         float* __restrict__ out, int n) {
    __shared__ float ws4[8][32][4];
    int wid = threadIdx.x >> 5, lane = threadIdx.x & 31;
    int node = blockIdx.x * 8 + wid;
    if (node >= n) return;
    float asn = 0.f, adn = 0.f;
    if (lane < 4) { asn = asv[node * 4 + lane]; adn = adv[node * 4 + lane]; }
    float m = lrelu(asn + adn);
    float adt[4], mt[4];
#pragma unroll
    for (int t = 0; t < 4; t++) {
        adt[t] = __shfl_sync(FULLM, adn, t);
        mt[t]  = __shfl_sync(FULLM, m, t);
    }
    float acc[7];
    int tk[7];
    const float* hself = Ht + (size_t)node * 224;
#pragma unroll
    for (int k = 0; k < 7; k++) {
        int c = lane + 32 * k;
        tk[k] = (c >= 12) + (c >= 42) + (c >= 102);
        acc[k] = hself[c];
    }
    float su0 = 0.f, su1 = 0.f, su2 = 0.f, su3 = 0.f;
    int beg = rowp[node], end = rowp[node + 1];
    for (int base = beg; base < end; base += 32) {
        int i = base + lane;
        int src_l = 0;
        float4 w4 = make_float4(0.f, 0.f, 0.f, 0.f);
        if (i < end) {
            src_l = col[i];
            float4 aq = *(const float4*)(asv + (size_t)src_l * 4);
            w4.x = __expf(lrelu(aq.x + adt[0]) - mt[0]);
            w4.y = __expf(lrelu(aq.y + adt[1]) - mt[1]);
            w4.z = __expf(lrelu(aq.z + adt[2]) - mt[2]);
            w4.w = __expf(lrelu(aq.w + adt[3]) - mt[3]);
            su0 += w4.x; su1 += w4.y; su2 += w4.z; su3 += w4.w;
        }
        *(float4*)&ws4[wid][lane][0] = w4;
        __syncwarp();
        int cnt = min(32, end - base);
#pragma unroll 2
        for (int e = 0; e < cnt; e++) {
            int se = __shfl_sync(FULLM, src_l, e);
            const float* hp = Ht + (size_t)se * 224;
#pragma unroll
            for (int k = 0; k < 7; k++)
                acc[k] = fmaf(ws4[wid][e][tk[k]], hp[lane + 32 * k], acc[k]);
        }
        __syncwarp();
    }
    float t0 = wredsum(su0) + 1.f + 1e-16f;
    float t1 = wredsum(su1) + 1.f + 1e-16f;
    float t2 = wredsum(su2) + 1.f + 1e-16f;
    float t3 = wredsum(su3) + 1.f + 1e-16f;
    float v[7];
#pragma unroll
    for (int k = 0; k < 7; k++) {
        float dk = (tk[k] == 0) ? t0 : (tk[k] == 1) ? t1 : (tk[k] == 2) ? t2 : t3;
        v[k] = acc[k] / dk + bias[lane + 32 * k];
    }
    const int Cc[4]  = {12, 30, 60, 120};
    const int Off[4] = {0, 12, 42, 102};
    size_t bases[4];
    bases[0] = 0; bases[1] = (size_t)n * 12; bases[2] = (size_t)n * 42; bases[3] = (size_t)n * 102;
#pragma unroll
    for (int t = 0; t < 4; t++) {
        float mx = -1e30f;
#pragma unroll
        for (int k = 0; k < 7; k++) { int c = lane + 32 * k; if (tk[k] == t && c < 222) mx = fmaxf(mx, v[k]); }
        mx = wredmax(mx);
        float se = 0.f;
#pragma unroll
        for (int k = 0; k < 7; k++) { int c = lane + 32 * k; if (tk[k] == t && c < 222) se += __expf(v[k] - mx); }
        se = wredsum(se);
        float lse = mx + __logf(se);
#pragma unroll
        for (int k = 0; k < 7; k++) {
            int c = lane + 32 * k;
            if (tk[k] == t && c < 222)
                out[bases[t] + (size_t)node * Cc[t] + (c - Off[t])] = v[k] - lse;
        }
    }
}

// ---------------- launch ----------------
extern "C" void kernel_launch(void* const* d_in, const int* in_sizes, int n_in,
                              void* d_out, int out_size) {
    const float* x   = (const float*)d_in[0];
    const int*   ei  = (const int*)d_in[1];
    const float* W1  = (const float*)d_in[2];
    const float* a1s = (const float*)d_in[3];
    const float* a1d = (const float*)d_in[4];
    const float* b1  = (const float*)d_in[5];
    const float* W2  = (const float*)d_in[6];
    const float* a2s = (const float*)d_in[7];
    const float* a2d = (const float*)d_in[8];
    const float* b2  = (const float*)d_in[9];
    const float* W_TL = (const float*)d_in[10], *as_TL = (const float*)d_in[11], *ad_TL = (const float*)d_in[12], *b_TL = (const float*)d_in[13];
    const float* W_YL = (const float*)d_in[14], *as_YL = (const float*)d_in[15], *ad_YL = (const float*)d_in[16], *b_YL = (const float*)d_in[17];
    const float* W_TS = (const float*)d_in[18], *as_TS = (const float*)d_in[19], *ad_TS = (const float*)d_in[20], *b_TS = (const float*)d_in[21];
    const float* W_TZ = (const float*)d_in[22], *as_TZ = (const float*)d_in[23], *ad_TZ = (const float*)d_in[24], *b_TZ = (const float*)d_in[25];

    int N = in_sizes[0] / 128;
    int E = in_sizes[1] / 2;

    float *bufA, *asv, *adv, *as4, *ad4, *acs, *acd, *bc;
    __nv_bfloat16 *xhi, *xlo, *hhi, *hlo, *B1hi, *B1lo, *B2hi, *B2lo, *Bthi, *Btlo;
    int *deg, *rowp, *cursor, *col;
    cudaGetSymbolAddress((void**)&bufA, g_bufA);
    cudaGetSymbolAddress((void**)&xhi, g_xhi);
    cudaGetSymbolAddress((void**)&xlo, g_xlo);
    cudaGetSymbolAddress((void**)&hhi, g_hhi);
    cudaGetSymbolAddress((void**)&hlo, g_hlo);
    cudaGetSymbolAddress((void**)&B1hi, g_B1hi);
    cudaGetSymbolAddress((void**)&B1lo, g_B1lo);
    cudaGetSymbolAddress((void**)&B2hi, g_B2hi);
    cudaGetSymbolAddress((void**)&B2lo, g_B2lo);
    cudaGetSymbolAddress((void**)&Bthi, g_Bthi);
    cudaGetSymbolAddress((void**)&Btlo, g_Btlo);
    cudaGetSymbolAddress((void**)&asv, g_as);
    cudaGetSymbolAddress((void**)&adv, g_ad);
    cudaGetSymbolAddress((void**)&as4, g_as4);
    cudaGetSymbolAddress((void**)&ad4, g_ad4);
    cudaGetSymbolAddress((void**)&acs, g_acs);
    cudaGetSymbolAddress((void**)&acd, g_acd);
    cudaGetSymbolAddress((void**)&bc, g_bc);
    cudaGetSymbolAddress((void**)&deg, g_deg);
    cudaGetSymbolAddress((void**)&rowp, g_rowp);
    cudaGetSymbolAddress((void**)&cursor, g_cursor);
    cudaGetSymbolAddress((void**)&col, g_col);

    cudaFuncSetAttribute(gemm_mma, cudaFuncAttributeMaxDynamicSharedMemorySize, SMEM_BYTES);

    // side streams + events (created once; graph fork/join pattern)
    static cudaStream_t s1 = 0, s2 = 0;
    static cudaEvent_t e0 = 0, eCsr = 0, ePk = 0;
    if (!s1) {
        cudaStreamCreateWithFlags(&s1, cudaStreamNonBlocking);
        cudaStreamCreateWithFlags(&s2, cudaStreamNonBlocking);
        cudaEventCreateWithFlags(&e0, cudaEventDisableTiming);
        cudaEventCreateWithFlags(&eCsr, cudaEventDisableTiming);
        cudaEventCreateWithFlags(&ePk, cudaEventDisableTiming);
    }

    int warpsGrid = (N + 7) / 8;
    int eGrid = (E + 255) / 256;
    int numTiles = ((N + 127) / 128) * 2;
    int gemmGrid = 296;                       // 2 CTAs/SM x 148 SMs, persistent

    // fork: side streams wait on origin
    cudaEventRecord(e0, 0);
    cudaStreamWaitEvent(s1, e0, 0);
    cudaStreamWaitEvent(s2, e0, 0);

    // s1: CSR build (independent of GEMM chain until agg1)
    zero_int<<<(N + 255) / 256, 256, 0, s1>>>(deg, N);
    count_deg<<<eGrid, 256, 0, s1>>>(ei, E, deg);
    scan_block<<<1, 1024, 0, s1>>>(deg, rowp, cursor, N);
    fill_col<<<eGrid, 256, 0, s1>>>(ei, E, cursor, col);
    cudaEventRecord(eCsr, s1);

    // s2: later-layer weight packs (needed before gemm2 / gemmT)
    pack_w<<<(256 * 256 + 255) / 256, 256, 0, s2>>>(W2, B2hi, B2lo, 256);
    pack_wt<<<(256 * 256 + 255) / 256, 256, 0, s2>>>(W_TL, W_YL, W_TS, W_TZ,
                                                     as_TL, as_YL, as_TS, as_TZ,
                                                     ad_TL, ad_YL, ad_TS, ad_TZ,
                                                     b_TL, b_YL, b_TS, b_TZ,
                                                     Bthi, Btlo, acs, acd, bc);
    cudaEventRecord(ePk, s2);

    // main: conv1 input prep + GEMM
    convert_x<<<(N * 32 + 255) / 256, 256>>>(x, xhi, xlo, N);
    pack_w<<<(256 * 128 + 255) / 256, 256>>>(W1, B1hi, B1lo, 128);
    gemm_mma<<<gemmGrid, 256, SMEM_BYTES>>>(xhi, xlo, B1hi, B1lo, bufA, N, 128, 256,
                                            numTiles, a1s, a1d, asv, adv, 1);
    // join CSR before aggregation
    cudaStreamWaitEvent(0, eCsr, 0);
    gat_agg_conv<<<warpsGrid, 256>>>(bufA, asv, adv, rowp, col, b1, hhi, hlo, N, 1);
    // join packs before conv2 GEMM
    cudaStreamWaitEvent(0, ePk, 0);
    gemm_mma<<<gemmGrid, 256, SMEM_BYTES>>>(hhi, hlo, B2hi, B2lo, bufA, N, 256, 256,
                                            numTiles, a2s, a2d, asv, adv, 1);
    gat_agg_conv<<<warpsGrid, 256>>>(bufA, asv, adv, rowp, col, b2, hhi, hlo, N, 0);
    // task GEMM with fused task-alpha epilogue (writes as4/ad4)
    gemm_mma<<<gemmGrid, 256, SMEM_BYTES>>>(hhi, hlo, Bthi, Btlo, bufA, N, 256, 224,
                                            numTiles, acs, acd, as4, ad4, 2);
    gat_task<<<warpsGrid, 256>>>(bufA, as4, ad4, rowp, col, bc, (float*)d_out, N);
}

// round 12
// speedup vs baseline: 1.0568x; 1.0568x over previous
#include <cuda_runtime.h>
#include <cuda_bf16.h>
#include <math.h>
#include <stdint.h>

#define NN 50000
#define NROWPAD 50048
#define EE 800000
#define FULLM 0xffffffffu

// ---------------- static scratch (no allocation allowed) ----------------
__device__ __align__(128) float g_bufA[NROWPAD * 256];      // fp32 GEMM outputs
__device__ __align__(128) __nv_bfloat16 g_xhi[NROWPAD * 128];
__device__ __align__(128) __nv_bfloat16 g_xlo[NROWPAD * 128];
__device__ __align__(128) __nv_bfloat16 g_hhi[NROWPAD * 256];
__device__ __align__(128) __nv_bfloat16 g_hlo[NROWPAD * 256];
__device__ __align__(128) __nv_bfloat16 g_B1hi[256 * 128];
__device__ __align__(128) __nv_bfloat16 g_B1lo[256 * 128];
__device__ __align__(128) __nv_bfloat16 g_B2hi[256 * 256];
__device__ __align__(128) __nv_bfloat16 g_B2lo[256 * 256];
__device__ __align__(128) __nv_bfloat16 g_Bthi[256 * 256];
__device__ __align__(128) __nv_bfloat16 g_Btlo[256 * 256];
__device__ float g_as[NN * 8];
__device__ float g_ad[NN * 8];
__device__ float g_as4[NN * 4];
__device__ float g_ad4[NN * 4];
__device__ float g_acs[224];
__device__ float g_acd[224];
__device__ float g_bc[224];
__device__ int g_deg[NN];
__device__ int g_rowp[NN + 1];
__device__ int g_cursor[NN];
__device__ int g_col[EE];

// ---------------- helpers ----------------
__device__ __forceinline__ float wredsum(float v) {
#pragma unroll
    for (int o = 16; o > 0; o >>= 1) v += __shfl_xor_sync(FULLM, v, o);
    return v;
}
__device__ __forceinline__ float wredmax(float v) {
#pragma unroll
    for (int o = 16; o > 0; o >>= 1) v = fmaxf(v, __shfl_xor_sync(FULLM, v, o));
    return v;
}
__device__ __forceinline__ float lrelu(float e) { return e > 0.f ? e : 0.2f * e; }
__device__ __forceinline__ unsigned su32(const void* p) {
    unsigned r;
    asm("{ .reg .u64 t; cvta.to.shared.u64 t, %1; cvt.u32.u64 %0, t; }" : "=r"(r) : "l"(p));
    return r;
}
__device__ __forceinline__ void splitbf(float v, __nv_bfloat16& h, __nv_bfloat16& l) {
    h = __float2bfloat16(v);
    l = __float2bfloat16(v - __bfloat162float(h));
}
__device__ __forceinline__ uint32_t pkbf(__nv_bfloat16 a, __nv_bfloat16 b) {
    __nv_bfloat162 t(a, b);
    return *(uint32_t*)&t;
}
__device__ __forceinline__ void cpa16b(uint32_t dst, const void* src) {
    asm volatile("cp.async.ca.shared.global [%0], [%1], 16;" :: "r"(dst), "l"(src));
}
#define CPA_COMMIT() asm volatile("cp.async.commit_group;" ::: "memory")
#define CPA_WAIT1()  asm volatile("cp.async.wait_group 1;" ::: "memory")

__device__ __forceinline__ void ldmx4(uint32_t* r, uint32_t addr) {
    asm volatile("ldmatrix.sync.aligned.m8n8.x4.shared.b16 {%0,%1,%2,%3}, [%4];"
                 : "=r"(r[0]), "=r"(r[1]), "=r"(r[2]), "=r"(r[3]) : "r"(addr));
}
__device__ __forceinline__ void mma16816(float* c, const uint32_t* a,
                                         uint32_t b0, uint32_t b1) {
    asm volatile(
        "mma.sync.aligned.m16n8k16.row.col.f32.bf16.bf16.f32 "
        "{%0,%1,%2,%3}, {%4,%5,%6,%7}, {%8,%9}, {%0,%1,%2,%3};"
        : "+f"(c[0]), "+f"(c[1]), "+f"(c[2]), "+f"(c[3])
        : "r"(a[0]), "r"(a[1]), "r"(a[2]), "r"(a[3]), "r"(b0), "r"(b1));
}

// ---------------- CSR build ----------------
__global__ void zero_int(int* p, int n) {
    int i = blockIdx.x * blockDim.x + threadIdx.x;
    if (i < n) p[i] = 0;
}
__global__ void count_deg(const int* __restrict__ ei, int E, int* deg) {
    int e = blockIdx.x * blockDim.x + threadIdx.x;
    if (e < E) atomicAdd(&deg[ei[E + e]], 1);
}
__global__ void scan_block(const int* __restrict__ deg, int* __restrict__ rowp,
                           int* __restrict__ cursor, int n) {
    __shared__ int sm[1024];
    int tid = threadIdx.x;
    int chunk = (n + 1023) >> 10;
    int start = tid * chunk;
    int s = 0;
    for (int i = 0; i < chunk; i++) { int id = start + i; if (id < n) s += deg[id]; }
    sm[tid] = s; __syncthreads();
    for (int o = 1; o < 1024; o <<= 1) {
        int t = (tid >= o) ? sm[tid - o] : 0;
        __syncthreads();
        sm[tid] += t;
        __syncthreads();
    }
    int run = sm[tid] - s;
    for (int i = 0; i < chunk; i++) {
        int id = start + i;
        if (id < n) { rowp[id] = run; cursor[id] = run; run += deg[id]; }
    }
    if (tid == 1023) rowp[n] = sm[1023];
}
__global__ void fill_col(const int* __restrict__ ei, int E, int* cursor, int* __restrict__ col) {
    int e = blockIdx.x * blockDim.x + threadIdx.x;
    if (e < E) {
        int s = ei[e];
        int d = ei[E + e];
        int p = atomicAdd(&cursor[d], 1);
        col[p] = s;
    }
}

// ---------------- input conversion fp32 -> bf16 hi/lo ----------------
__global__ void convert_x(const float* __restrict__ x, __nv_bfloat16* __restrict__ xhi,
                          __nv_bfloat16* __restrict__ xlo, int n) {
    int idx = blockIdx.x * blockDim.x + threadIdx.x;   // 4 floats each
    if (idx >= n * 32) return;
    int row = idx >> 5, c4 = (idx & 31) << 2;
    float4 v = *(const float4*)(x + (size_t)row * 128 + c4);
    __nv_bfloat16 h0, l0, h1, l1, h2, l2, h3, l3;
    splitbf(v.x, h0, l0); splitbf(v.y, h1, l1);
    splitbf(v.z, h2, l2); splitbf(v.w, h3, l3);
    uint2 hw = make_uint2(pkbf(h0, h1), pkbf(h2, h3));
    uint2 lw = make_uint2(pkbf(l0, l1), pkbf(l2, l3));
    *(uint2*)(xhi + (size_t)row * 128 + c4) = hw;
    *(uint2*)(xlo + (size_t)row * 128 + c4) = lw;
}

// ---------------- weight packs: W[K][256] -> B[n][K] bf16 hi/lo (transposed) ----------
__global__ void pack_w(const float* __restrict__ W, __nv_bfloat16* __restrict__ bh,
                       __nv_bfloat16* __restrict__ bl, int K) {
    int idx = blockIdx.x * blockDim.x + threadIdx.x;
    if (idx >= 256 * K) return;
    int n = idx / K, k = idx % K;
    float v = W[(size_t)k * 256 + n];
    __nv_bfloat16 h, l;
    splitbf(v, h, l);
    bh[idx] = h; bl[idx] = l;
}
__global__ void pack_wt(const float* __restrict__ W0, const float* __restrict__ W1,
                        const float* __restrict__ W2, const float* __restrict__ W3,
                        const float* __restrict__ s0, const float* __restrict__ s1,
                        const float* __restrict__ s2, const float* __restrict__ s3,
                        const float* __restrict__ d0, const float* __restrict__ d1,
                        const float* __restrict__ d2, const float* __restrict__ d3,
                        const float* __restrict__ b0, const float* __restrict__ b1,
                        const float* __restrict__ b2, const float* __restrict__ b3,
                        __nv_bfloat16* __restrict__ bh, __nv_bfloat16* __restrict__ bl,
                        float* __restrict__ acs, float* __restrict__ acd,
                        float* __restrict__ bc) {
    int idx = blockIdx.x * blockDim.x + threadIdx.x;
    if (idx >= 256 * 256) return;
    int n = idx >> 8, k = idx & 255;
    float v = 0.f;
    if (n < 12) v = W0[k * 12 + n];
    else if (n < 42) v = W1[k * 30 + (n - 12)];
    else if (n < 102) v = W2[k * 60 + (n - 42)];
    else if (n < 222) v = W3[k * 120 + (n - 102)];
    __nv_bfloat16 h, l;
    splitbf(v, h, l);
    bh[idx] = h; bl[idx] = l;
    if (k == 0 && n < 224) {
        float s = 0.f, d = 0.f, b = 0.f;
        if (n < 12)       { s = s0[n];        d = d0[n];        b = b0[n]; }
        else if (n < 42)  { s = s1[n - 12];   d = d1[n - 12];   b = b1[n - 12]; }
        else if (n < 102) { s = s2[n - 42];   d = d2[n - 42];   b = b2[n - 42]; }
        else if (n < 222) { s = s3[n - 102];  d = d3[n - 102];  b = b3[n - 102]; }
        acs[n] = s; acd[n] = d; bc[n] = b;
    }
}

// ---------------- bf16x3 GEMM via mma.sync: C[M,Nout] = A[M,K] * W ----------------
// CTA tile 128x128, warp tile 32x64 (4M x 2N warps), K chunk 32, cp.async dbl buffer.
#define STG_ELEMS 20480
#define SMEM_BYTES (2 * STG_ELEMS * 2)

__global__ __launch_bounds__(256, 2) void gemm_mma(
    const __nv_bfloat16* __restrict__ Ah, const __nv_bfloat16* __restrict__ Al,
    const __nv_bfloat16* __restrict__ Bh, const __nv_bfloat16* __restrict__ Bl,
    float* __restrict__ C, int M, int K, int Nout,
    const float* __restrict__ a_s, const float* __restrict__ a_d,
    float* __restrict__ as_out, float* __restrict__ ad_out, int do_alpha) {
    extern __shared__ __nv_bfloat16 smem[];
    int tid = threadIdx.x, wid = tid >> 5, lane = tid & 31;
    int rowBase = blockIdx.y * 128, colBase = blockIdx.x * 128;
    int warpM = (wid & 3) * 32, warpN = (wid >> 2) * 64;
    int g = lane >> 2, tg = lane & 3;

    float c[2][8][4];
#pragma unroll
    for (int mt = 0; mt < 2; mt++)
#pragma unroll
        for (int nt = 0; nt < 8; nt++)
#pragma unroll
            for (int j = 0; j < 4; j++) c[mt][nt][j] = 0.f;

    auto issue = [&](int t, int buf) {
        int kc = t << 5;
        uint32_t base = buf * STG_ELEMS;
#pragma unroll
        for (int i = 0; i < 2; i++) {
            int q = tid + i * 256;
            int r = q >> 2, seg = (q & 3) << 3;
            size_t aoff = (size_t)(rowBase + r) * K + kc + seg;
            size_t boff = (size_t)(colBase + r) * K + kc + seg;
            uint32_t doff = base + (uint32_t)(r * 40 + seg);
            cpa16b(su32(&smem[doff]), Ah + aoff);
            cpa16b(su32(&smem[5120 + doff]), Al + aoff);
            cpa16b(su32(&smem[10240 + doff]), Bh + boff);
            cpa16b(su32(&smem[15360 + doff]), Bl + boff);
        }
        CPA_COMMIT();
    };

    int T = K >> 5;
    issue(0, 0);
    for (int t = 0; t < T; t++) {
        if (t + 1 < T) issue(t + 1, (t + 1) & 1);
        else CPA_COMMIT();
        CPA_WAIT1();
        __syncthreads();
        uint32_t sb = su32(&smem[(t & 1) * STG_ELEMS]);
#pragma unroll
        for (int ks = 0; ks < 32; ks += 16) {
            uint32_t aHi[2][4], aLo[2][4];
#pragma unroll
            for (int mt = 0; mt < 2; mt++) {
                uint32_t addr = sb + ((uint32_t)((warpM + mt * 16 + (lane & 15)) * 40
                                                 + ks + ((lane >> 4) & 1) * 8) << 1);
                ldmx4(aHi[mt], addr);
                ldmx4(aLo[mt], addr + 5120 * 2);
            }
#pragma unroll
            for (int nb = 0; nb < 4; nb++) {
                uint32_t bHi[4], bLo[4];
                uint32_t addr = sb + ((uint32_t)(10240
                                  + (warpN + nb * 16 + (lane & 7) + ((lane >> 4) & 1) * 8) * 40
                                  + ks + ((lane >> 3) & 1) * 8) << 1);
                ldmx4(bHi, addr);
                ldmx4(bLo, addr + 5120 * 2);
#pragma unroll
                for (int mt = 0; mt < 2; mt++)
#pragma unroll
                    for (int half = 0; half < 2; half++) {
                        int nt = nb * 2 + half, s = half * 2;
                        mma16816(c[mt][nt], aHi[mt], bHi[s], bHi[s + 1]);
                        mma16816(c[mt][nt], aHi[mt], bLo[s], bLo[s + 1]);
                        mma16816(c[mt][nt], aLo[mt], bHi[s], bHi[s + 1]);
                    }
            }
        }
        __syncthreads();
    }

    // store C (fp32)
#pragma unroll
    for (int mt = 0; mt < 2; mt++) {
        int r0 = rowBase + warpM + mt * 16 + g;
#pragma unroll
        for (int nt = 0; nt < 8; nt++) {
            int col = colBase + warpN + nt * 8 + tg * 2;
            if (col < Nout) {
                if (r0 < M)
                    *(float2*)(C + (size_t)r0 * Nout + col) = make_float2(c[mt][nt][0], c[mt][nt][1]);
                if (r0 + 8 < M)
                    *(float2*)(C + (size_t)(r0 + 8) * Nout + col) = make_float2(c[mt][nt][2], c[mt][nt][3]);
            }
        }
    }
    // fused per-head alpha (conv layers): warp tile 64 cols = 2 heads (32 cols each)
    if (do_alpha) {
#pragma unroll
        for (int hh = 0; hh < 2; hh++) {
            int head = ((colBase + warpN) >> 5) + hh;
#pragma unroll
            for (int mt = 0; mt < 2; mt++) {
                float sl = 0.f, sh = 0.f, dl = 0.f, dh = 0.f;
#pragma unroll
                for (int q = 0; q < 4; q++) {
                    int nt = hh * 4 + q;
                    int col = colBase + warpN + nt * 8 + tg * 2;
                    float s0 = a_s[col], s1 = a_s[col + 1];
                    float d0 = a_d[col], d1 = a_d[col + 1];
                    sl += c[mt][nt][0] * s0 + c[mt][nt][1] * s1;
                    sh += c[mt][nt][2] * s0 + c[mt][nt][3] * s1;
                    dl += c[mt][nt][0] * d0 + c[mt][nt][1] * d1;
                    dh += c[mt][nt][2] * d0 + c[mt][nt][3] * d1;
                }
                sl += __shfl_xor_sync(FULLM, sl, 1); sl += __shfl_xor_sync(FULLM, sl, 2);
                sh += __shfl_xor_sync(FULLM, sh, 1); sh += __shfl_xor_sync(FULLM, sh, 2);
                dl += __shfl_xor_sync(FULLM, dl, 1); dl += __shfl_xor_sync(FULLM, dl, 2);
                dh += __shfl_xor_sync(FULLM, dh, 1); dh += __shfl_xor_sync(FULLM, dh, 2);
                if (tg == 0) {
                    int r0 = rowBase + warpM + mt * 16 + g;
                    if (r0 < M)     { as_out[r0 * 8 + head] = sl;       ad_out[r0 * 8 + head] = dl; }
                    if (r0 + 8 < M) { as_out[(r0 + 8) * 8 + head] = sh; ad_out[(r0 + 8) * 8 + head] = dh; }
                }
            }
        }
    }
}

// ---------------- GAT aggregation (conv): dense lane mapping ----------------
// Lane owns channels [lane*4 .. lane*4+3] (head lane>>3) and
// [128+lane*4 .. 128+lane*4+3] (head 4+(lane>>3)). Each edge gather = 2 dense
// 512B float4 warp loads (8 cache lines total vs 16 with strided mapping).
__global__ void gat_agg_conv(const float* __restrict__ h, const float* __restrict__ asv,
                             const float* __restrict__ adv, const int* __restrict__ rowp,
                             const int* __restrict__ col, const float* __restrict__ bias,
                             __nv_bfloat16* __restrict__ outHi,
                             __nv_bfloat16* __restrict__ outLo, int n, int do_elu) {
    __shared__ float ws[8][32][8];
    int wid = threadIdx.x >> 5, lane = threadIdx.x & 31;
    int node = blockIdx.x * 8 + wid;
    if (node >= n) return;
    int head1 = lane >> 3;
    int head2 = 4 + head1;
    float asn = 0.f, adn = 0.f;
    if (lane < 8) { asn = asv[node * 8 + lane]; adn = adv[node * 8 + lane]; }
    float m = lrelu(asn + adn);               // shift (softmax invariant); w_self = 1
    float adh[8], mh[8];
#pragma unroll
    for (int k = 0; k < 8; k++) {
        adh[k] = __shfl_sync(FULLM, adn, k);
        mh[k]  = __shfl_sync(FULLM, m, k);
    }
    const float* hs0 = h + (size_t)node * 256;
    float4 acc0 = *(const float4*)(hs0 + lane * 4);          // self loop (w=1)
    float4 acc1 = *(const float4*)(hs0 + 128 + lane * 4);
    float ssum1 = 1.f, ssum2 = 1.f;
    int beg = rowp[node], end = rowp[node + 1];
    for (int base = beg; base < end; base += 32) {
        int i = base + lane;
        int src_l = 0;
        float4 wlo = make_float4(0.f, 0.f, 0.f, 0.f), whi = wlo;
        if (i < end) {
            src_l = col[i];
            const float4* ap = (const float4*)(asv + (size_t)src_l * 8);
            float4 a0 = ap[0], a1 = ap[1];
            wlo.x = __expf(lrelu(a0.x + adh[0]) - mh[0]);
            wlo.y = __expf(lrelu(a0.y + adh[1]) - mh[1]);
            wlo.z = __expf(lrelu(a0.z + adh[2]) - mh[2]);
            wlo.w = __expf(lrelu(a0.w + adh[3]) - mh[3]);
            whi.x = __expf(lrelu(a1.x + adh[4]) - mh[4]);
            whi.y = __expf(lrelu(a1.y + adh[5]) - mh[5]);
            whi.z = __expf(lrelu(a1.z + adh[6]) - mh[6]);
            whi.w = __expf(lrelu(a1.w + adh[7]) - mh[7]);
        }
        *(float4*)&ws[wid][lane][0] = wlo;
        *(float4*)&ws[wid][lane][4] = whi;
        __syncwarp();
        int cnt = min(32, end - base);
#pragma unroll 4
        for (int e = 0; e < cnt; e++) {
            float we1 = ws[wid][e][head1];
            float we2 = ws[wid][e][head2];
            int se = __shfl_sync(FULLM, src_l, e);
            ssum1 += we1;
            ssum2 += we2;
            const float* hp = h + (size_t)se * 256;
            float4 v0 = *(const float4*)(hp + lane * 4);
            float4 v1 = *(const float4*)(hp + 128 + lane * 4);
            acc0.x = fmaf(we1, v0.x, acc0.x); acc0.y = fmaf(we1, v0.y, acc0.y);
            acc0.z = fmaf(we1, v0.z, acc0.z); acc0.w = fmaf(we1, v0.w, acc0.w);
            acc1.x = fmaf(we2, v1.x, acc1.x); acc1.y = fmaf(we2, v1.y, acc1.y);
            acc1.z = fmaf(we2, v1.z, acc1.z); acc1.w = fmaf(we2, v1.w, acc1.w);
        }
        __syncwarp();
    }
    float inv1 = 1.f / (ssum1 + 1e-16f);
    float inv2 = 1.f / (ssum2 + 1e-16f);
    float4 b0 = *(const float4*)(bias + lane * 4);
    float4 b1v = *(const float4*)(bias + 128 + lane * 4);
    float o[8];
    o[0] = acc0.x * inv1 + b0.x;  o[1] = acc0.y * inv1 + b0.y;
    o[2] = acc0.z * inv1 + b0.z;  o[3] = acc0.w * inv1 + b0.w;
    o[4] = acc1.x * inv2 + b1v.x; o[5] = acc1.y * inv2 + b1v.y;
    o[6] = acc1.z * inv2 + b1v.z; o[7] = acc1.w * inv2 + b1v.w;
    if (do_elu) {
#pragma unroll
        for (int j = 0; j < 8; j++) o[j] = o[j] > 0.f ? o[j] : expm1f(o[j]);
    }
    uint32_t hw[4], lw[4];
#pragma unroll
    for (int j = 0; j < 4; j++) {
        __nv_bfloat16 ha, la, hb, lb;
        splitbf(o[2 * j], ha, la);
        splitbf(o[2 * j + 1], hb, lb);
        hw[j] = pkbf(ha, hb);
        lw[j] = pkbf(la, lb);
    }
    size_t off0 = (size_t)node * 256 + lane * 4;
    size_t off1 = (size_t)node * 256 + 128 + lane * 4;
    *(uint2*)(outHi + off0) = make_uint2(hw[0], hw[1]);
    *(uint2*)(outHi + off1) = make_uint2(hw[2], hw[3]);
    *(uint2*)(outLo + off0) = make_uint2(lw[0], lw[1]);
    *(uint2*)(outLo + off1) = make_uint2(lw[2], lw[3]);
}

// ---------------- per-node attention scalars (4 task heads) ----------------
__global__ void alpha_task(const float* __restrict__ Ht, const float* __restrict__ acs,
                           const float* __restrict__ acd, float* __restrict__ as4,
                           float* __restrict__ ad4, int n) {
    int warp = (blockIdx.x * blockDim.x + threadIdx.x) >> 5;
    int lane = threadIdx.x & 31;
    if (warp >= n) return;
    const float* row = Ht + (size_t)warp * 224;
    float s0 = 0, s1 = 0, s2 = 0, s3 = 0, d0 = 0, d1 = 0, d2 = 0, d3 = 0;
#pragma unroll
    for (int k = 0; k < 7; k++) {
        int c = lane + 32 * k;
        float hv = row[c];
        float vs = hv * acs[c], vd = hv * acd[c];
        int t = (c >= 12) + (c >= 42) + (c >= 102);
        if (t == 0) { s0 += vs; d0 += vd; }
        else if (t == 1) { s1 += vs; d1 += vd; }
        else if (t == 2) { s2 += vs; d2 += vd; }
        else { s3 += vs; d3 += vd; }
    }
    s0 = wredsum(s0); s1 = wredsum(s1); s2 = wredsum(s2); s3 = wredsum(s3);
    d0 = wredsum(d0); d1 = wredsum(d1); d2 = wredsum(d2); d3 = wredsum(d3);
    if (lane == 0) {
        as4[warp * 4 + 0] = s0; as4[warp * 4 + 1] = s1; as4[warp * 4 + 2] = s2; as4[warp * 4 + 3] = s3;
        ad4[warp * 4 + 0] = d0; ad4[warp * 4 + 1] = d1; ad4[warp * 4 + 2] = d2; ad4[warp * 4 + 3] = d3;
    }
}

// ---------------- fused task aggregation + log_softmax -> d_out ----------------
__global__ void gat_task(const float* __restrict__ Ht, const float* __restrict__ asv,
                         const float* __restrict__ adv, const int* __restrict__ rowp,
                         const int* __restrict__ col, const float* __restrict__ bias,
                         float* __restrict__ out, int n) {
    __shared__ float ws4[8][32][4];
    int wid = threadIdx.x >> 5, lane = threadIdx.x & 31;
    int node = blockIdx.x * 8 + wid;
    if (node >= n) return;
    float asn = 0.f, adn = 0.f;
    if (lane < 4) { asn = asv[node * 4 + lane]; adn = adv[node * 4 + lane]; }
    float m = lrelu(asn + adn);
    float adt[4], mt[4];
#pragma unroll
    for (int t = 0; t < 4; t++) {
        adt[t] = __shfl_sync(FULLM, adn, t);
        mt[t]  = __shfl_sync(FULLM, m, t);
    }
    float acc[7];
    int tk[7];
    const float* hself = Ht + (size_t)node * 224;
#pragma unroll
    for (int k = 0; k < 7; k++) {
        int c = lane + 32 * k;
        tk[k] = (c >= 12) + (c >= 42) + (c >= 102);
        acc[k] = hself[c];
    }
    float su0 = 0.f, su1 = 0.f, su2 = 0.f, su3 = 0.f;
    int beg = rowp[node], end = rowp[node + 1];
    for (int base = beg; base < end; base += 32) {
        int i = base + lane;
        int src_l = 0;
        float4 w4 = make_float4(0.f, 0.f, 0.f, 0.f);
        if (i < end) {
            src_l = col[i];
            float4 aq = *(const float4*)(asv + (size_t)src_l * 4);
            w4.x = __expf(lrelu(aq.x + adt[0]) - mt[0]);
            w4.y = __expf(lrelu(aq.y + adt[1]) - mt[1]);
            w4.z = __expf(lrelu(aq.z + adt[2]) - mt[2]);
            w4.w = __expf(lrelu(aq.w + adt[3]) - mt[3]);
            su0 += w4.x; su1 += w4.y; su2 += w4.z; su3 += w4.w;
        }
        *(float4*)&ws4[wid][lane][0] = w4;
        __syncwarp();
        int cnt = min(32, end - base);
#pragma unroll 2
        for (int e = 0; e < cnt; e++) {
            int se = __shfl_sync(FULLM, src_l, e);
            const float* hp = Ht + (size_t)se * 224;
#pragma unroll
            for (int k = 0; k < 7; k++)
                acc[k] = fmaf(ws4[wid][e][tk[k]], hp[lane + 32 * k], acc[k]);
        }
        __syncwarp();
    }
    float t0 = wredsum(su0) + 1.f + 1e-16f;
    float t1 = wredsum(su1) + 1.f + 1e-16f;
    float t2 = wredsum(su2) + 1.f + 1e-16f;
    float t3 = wredsum(su3) + 1.f + 1e-16f;
    float v[7];
#pragma unroll
    for (int k = 0; k < 7; k++) {
        float dk = (tk[k] == 0) ? t0 : (tk[k] == 1) ? t1 : (tk[k] == 2) ? t2 : t3;
        v[k] = acc[k] / dk + bias[lane + 32 * k];
    }
    const int Cc[4]  = {12, 30, 60, 120};
    const int Off[4] = {0, 12, 42, 102};
    size_t bases[4];
    bases[0] = 0; bases[1] = (size_t)n * 12; bases[2] = (size_t)n * 42; bases[3] = (size_t)n * 102;
#pragma unroll
    for (int t = 0; t < 4; t++) {
        float mx = -1e30f;
#pragma unroll
        for (int k = 0; k < 7; k++) { int c = lane + 32 * k; if (tk[k] == t && c < 222) mx = fmaxf(mx, v[k]); }
        mx = wredmax(mx);
        float se = 0.f;
#pragma unroll
        for (int k = 0; k < 7; k++) { int c = lane + 32 * k; if (tk[k] == t && c < 222) se += __expf(v[k] - mx); }
        se = wredsum(se);
        float lse = mx + __logf(se);
#pragma unroll
        for (int k = 0; k < 7; k++) {
            int c = lane + 32 * k;
            if (tk[k] == t && c < 222)
                out[bases[t] + (size_t)node * Cc[t] + (c - Off[t])] = v[k] - lse;
        }
    }
}

// ---------------- launch ----------------
extern "C" void kernel_launch(void* const* d_in, const int* in_sizes, int n_in,
                              void* d_out, int out_size) {
    const float* x   = (const float*)d_in[0];
    const int*   ei  = (const int*)d_in[1];
    const float* W1  = (const float*)d_in[2];
    const float* a1s = (const float*)d_in[3];
    const float* a1d = (const float*)d_in[4];
    const float* b1  = (const float*)d_in[5];
    const float* W2  = (const float*)d_in[6];
    const float* a2s = (const float*)d_in[7];
    const float* a2d = (const float*)d_in[8];
    const float* b2  = (const float*)d_in[9];
    const float* W_TL = (const float*)d_in[10], *as_TL = (const float*)d_in[11], *ad_TL = (const float*)d_in[12], *b_TL = (const float*)d_in[13];
    const float* W_YL = (const float*)d_in[14], *as_YL = (const float*)d_in[15], *ad_YL = (const float*)d_in[16], *b_YL = (const float*)d_in[17];
    const float* W_TS = (const float*)d_in[18], *as_TS = (const float*)d_in[19], *ad_TS = (const float*)d_in[20], *b_TS = (const float*)d_in[21];
    const float* W_TZ = (const float*)d_in[22], *as_TZ = (const float*)d_in[23], *ad_TZ = (const float*)d_in[24], *b_TZ = (const float*)d_in[25];

    int N = in_sizes[0] / 128;
    int E = in_sizes[1] / 2;

    float *bufA, *asv, *adv, *as4, *ad4, *acs, *acd, *bc;
    __nv_bfloat16 *xhi, *xlo, *hhi, *hlo, *B1hi, *B1lo, *B2hi, *B2lo, *Bthi, *Btlo;
    int *deg, *rowp, *cursor, *col;
    cudaGetSymbolAddress((void**)&bufA, g_bufA);
    cudaGetSymbolAddress((void**)&xhi, g_xhi);
    cudaGetSymbolAddress((void**)&xlo, g_xlo);
    cudaGetSymbolAddress((void**)&hhi, g_hhi);
    cudaGetSymbolAddress((void**)&hlo, g_hlo);
    cudaGetSymbolAddress((void**)&B1hi, g_B1hi);
    cudaGetSymbolAddress((void**)&B1lo, g_B1lo);
    cudaGetSymbolAddress((void**)&B2hi, g_B2hi);
    cudaGetSymbolAddress((void**)&B2lo, g_B2lo);
    cudaGetSymbolAddress((void**)&Bthi, g_Bthi);
    cudaGetSymbolAddress((void**)&Btlo, g_Btlo);
    cudaGetSymbolAddress((void**)&asv, g_as);
    cudaGetSymbolAddress((void**)&adv, g_ad);
    cudaGetSymbolAddress((void**)&as4, g_as4);
    cudaGetSymbolAddress((void**)&ad4, g_ad4);
    cudaGetSymbolAddress((void**)&acs, g_acs);
    cudaGetSymbolAddress((void**)&acd, g_acd);
    cudaGetSymbolAddress((void**)&bc, g_bc);
    cudaGetSymbolAddress((void**)&deg, g_deg);
    cudaGetSymbolAddress((void**)&rowp, g_rowp);
    cudaGetSymbolAddress((void**)&cursor, g_cursor);
    cudaGetSymbolAddress((void**)&col, g_col);

    cudaFuncSetAttribute(gemm_mma, cudaFuncAttributeMaxDynamicSharedMemorySize, SMEM_BYTES);

    // side streams + events (created once; graph fork/join pattern)
    static cudaStream_t s1 = 0, s2 = 0;
    static cudaEvent_t e0 = 0, eCsr = 0, ePk = 0;
    if (!s1) {
        cudaStreamCreateWithFlags(&s1, cudaStreamNonBlocking);
        cudaStreamCreateWithFlags(&s2, cudaStreamNonBlocking);
        cudaEventCreateWithFlags(&e0, cudaEventDisableTiming);
        cudaEventCreateWithFlags(&eCsr, cudaEventDisableTiming);
        cudaEventCreateWithFlags(&ePk, cudaEventDisableTiming);
    }

    int warpsGrid = (N + 7) / 8;
    int eGrid = (E + 255) / 256;
    dim3 gGemm(2, (N + 127) / 128);

    // fork: side streams wait on origin
    cudaEventRecord(e0, 0);
    cudaStreamWaitEvent(s1, e0, 0);
    cudaStreamWaitEvent(s2, e0, 0);

    // s1: CSR build (independent of GEMM chain until agg1)
    zero_int<<<(N + 255) / 256, 256, 0, s1>>>(deg, N);
    count_deg<<<eGrid, 256, 0, s1>>>(ei, E, deg);
    scan_block<<<1, 1024, 0, s1>>>(deg, rowp, cursor, N);
    fill_col<<<eGrid, 256, 0, s1>>>(ei, E, cursor, col);
    cudaEventRecord(eCsr, s1);

    // s2: later-layer weight packs (needed before gemm2 / gemmT)
    pack_w<<<(256 * 256 + 255) / 256, 256, 0, s2>>>(W2, B2hi, B2lo, 256);
    pack_wt<<<(256 * 256 + 255) / 256, 256, 0, s2>>>(W_TL, W_YL, W_TS, W_TZ,
                                                     as_TL, as_YL, as_TS, as_TZ,
                                                     ad_TL, ad_YL, ad_TS, ad_TZ,
                                                     b_TL, b_YL, b_TS, b_TZ,
                                                     Bthi, Btlo, acs, acd, bc);
    cudaEventRecord(ePk, s2);

    // main: conv1 input prep + GEMM
    convert_x<<<(N * 32 + 255) / 256, 256>>>(x, xhi, xlo, N);
    pack_w<<<(256 * 128 + 255) / 256, 256>>>(W1, B1hi, B1lo, 128);
    gemm_mma<<<gGemm, 256, SMEM_BYTES>>>(xhi, xlo, B1hi, B1lo, bufA, N, 128, 256,
                                         a1s, a1d, asv, adv, 1);
    // join CSR before aggregation
    cudaStreamWaitEvent(0, eCsr, 0);
    gat_agg_conv<<<warpsGrid, 256>>>(bufA, asv, adv, rowp, col, b1, hhi, hlo, N, 1);
    // join packs before conv2 GEMM
    cudaStreamWaitEvent(0, ePk, 0);
    gemm_mma<<<gGemm, 256, SMEM_BYTES>>>(hhi, hlo, B2hi, B2lo, bufA, N, 256, 256,
                                         a2s, a2d, asv, adv, 1);
    gat_agg_conv<<<warpsGrid, 256>>>(bufA, asv, adv, rowp, col, b2, hhi, hlo, N, 0);
    gemm_mma<<<gGemm, 256, SMEM_BYTES>>>(hhi, hlo, Bthi, Btlo, bufA, N, 256, 224,
                                         (const float*)0, (const float*)0,
                                         (float*)0, (float*)0, 0);
    alpha_task<<<warpsGrid, 256>>>(bufA, acs, acd, as4, ad4, N);
    gat_task<<<warpsGrid, 256>>>(bufA, as4, ad4, rowp, col, bc, (float*)d_out, N);
}